// round 3
// baseline (speedup 1.0000x reference)
#include <cuda_runtime.h>
#include <cuda_bf16.h>
#include <math.h>

#define ATOMS_N 48
#define NSPEC 4
#define RAD_LEN 64
#define ANG_SUB 32
#define ANG_LEN 320
#define AEV_LEN 384
#define RCR_F 5.2f
#define RCA_F 3.5f
#define PI_F 3.14159265358979323846f

__global__ __launch_bounds__(128)
void aev_kernel(const float* __restrict__ coords,
                const float* __restrict__ EtaR,
                const float* __restrict__ ShfR,
                const float* __restrict__ EtaA,
                const float* __restrict__ Zeta,
                const float* __restrict__ ShfA,
                const float* __restrict__ ShfZ,
                const int*   __restrict__ species,
                float* __restrict__ out)
{
    __shared__ float sc[ATOMS_N * 3];
    __shared__ float ddx[ATOMS_N], ddy[ATOMS_N], ddz[ATOMS_N];
    __shared__ float dd[ATOMS_N], fcA[ATOMS_N], fcR[ATOMS_N];
    __shared__ int   ssp[ATOMS_N], nidx[ATOMS_N];
    __shared__ int   slist[NSPEC][ATOMS_N];
    __shared__ int   scnt4[NSPEC];
    __shared__ int   ncnt;
    __shared__ float acc[AEV_LEN];
    __shared__ float shR[16], shA[4], czv[8], szv[8];
    __shared__ float sP[3]; // etaR, etaA, zeta

    const int tid = threadIdx.x;
    const int m  = blockIdx.x / ATOMS_N;
    const int ci = blockIdx.x % ATOMS_N;

    // ---- coalesced loads + params + zero accumulator ----
    sc[tid] = coords[m * 144 + tid];
    if (tid < 16) sc[128 + tid] = coords[m * 144 + 128 + tid];
    if (tid < ATOMS_N) ssp[tid] = species[m * ATOMS_N + tid];
    if (tid >= 64 && tid < 80) shR[tid - 64] = ShfR[tid - 64];
    if (tid >= 80 && tid < 84) shA[tid - 80] = ShfA[tid - 80];
    if (tid >= 88 && tid < 96) {
        float v = ShfZ[tid - 88];
        czv[tid - 88] = cosf(v);
        szv[tid - 88] = sinf(v);
    }
    if (tid == 96) sP[0] = EtaR[0];
    if (tid == 97) sP[1] = EtaA[0];
    if (tid == 98) sP[2] = Zeta[0];
    acc[tid] = 0.0f; acc[tid + 128] = 0.0f; acc[tid + 256] = 0.0f;
    __syncthreads();

    // ---- warp 0: geometry for all 48 atoms + ballot compaction ----
    if (tid < 32) {
        const int lane = tid;
        const unsigned lt = (1u << lane) - 1u;
        const float cx = sc[3 * ci], cy = sc[3 * ci + 1], cz = sc[3 * ci + 2];

        float x0 = sc[3 * lane] - cx;
        float y0 = sc[3 * lane + 1] - cy;
        float z0 = sc[3 * lane + 2] - cz;
        float d0 = sqrtf(x0 * x0 + y0 * y0 + z0 * z0);
        ddx[lane] = x0; ddy[lane] = y0; ddz[lane] = z0; dd[lane] = d0;
        fcR[lane] = 0.5f * __cosf(d0 * (PI_F / RCR_F)) + 0.5f;
        fcA[lane] = 0.5f * __cosf(d0 * (PI_F / RCA_F)) + 0.5f;

        float d1 = 1e30f;
        const int j1 = 32 + lane;
        if (lane < 16) {
            float x1 = sc[3 * j1] - cx;
            float y1 = sc[3 * j1 + 1] - cy;
            float z1 = sc[3 * j1 + 2] - cz;
            d1 = sqrtf(x1 * x1 + y1 * y1 + z1 * z1);
            ddx[j1] = x1; ddy[j1] = y1; ddz[j1] = z1; dd[j1] = d1;
            fcR[j1] = 0.5f * __cosf(d1 * (PI_F / RCR_F)) + 0.5f;
            fcA[j1] = 0.5f * __cosf(d1 * (PI_F / RCA_F)) + 0.5f;
        }

        // angular neighbor list
        bool v0 = (lane != ci) && (d0 <= RCA_F);
        bool v1 = (lane < 16) && (j1 != ci) && (d1 <= RCA_F);
        unsigned m0 = __ballot_sync(0xffffffffu, v0);
        unsigned m1 = __ballot_sync(0xffffffffu, v1);
        int c0 = __popc(m0);
        if (v0) nidx[__popc(m0 & lt)] = lane;
        if (v1) nidx[c0 + __popc(m1 & lt)] = j1;
        if (lane == 0) ncnt = c0 + __popc(m1);

        // per-species radial lists
        const int sp0 = ssp[lane];
        const int sp1 = (lane < 16) ? ssp[j1] : -1;
        const bool r0 = (lane != ci) && (d0 <= RCR_F);
        const bool r1 = (lane < 16) && (j1 != ci) && (d1 <= RCR_F);
        #pragma unroll
        for (int s = 0; s < NSPEC; s++) {
            bool a0v = r0 && (sp0 == s);
            bool a1v = r1 && (sp1 == s);
            unsigned b0 = __ballot_sync(0xffffffffu, a0v);
            unsigned b1 = __ballot_sync(0xffffffffu, a1v);
            int cc0 = __popc(b0);
            if (a0v) slist[s][__popc(b0 & lt)] = lane;
            if (a1v) slist[s][cc0 + __popc(b1 & lt)] = j1;
            if (lane == 0) scnt4[s] = cc0 + __popc(b1);
        }
    }
    __syncthreads();

    // ---- fused phase: warp 0 radial (species lists), warps 1-3 angular ----
    if (tid < 32) {
        const float er = sP[0];
        #pragma unroll
        for (int half = 0; half < 2; half++) {
            const int c = tid + 32 * half;
            const int s = c >> 4;
            const float sh = shR[c & 15];
            const int cnt = scnt4[s];
            float sum0 = 0.0f, sum1 = 0.0f;
            int i = 0;
            for (; i + 1 < cnt; i += 2) {
                int ja = slist[s][i], jb = slist[s][i + 1];
                float ta = dd[ja] - sh, tb = dd[jb] - sh;
                sum0 += __expf(-er * ta * ta) * fcR[ja];
                sum1 += __expf(-er * tb * tb) * fcR[jb];
            }
            if (i < cnt) {
                int ja = slist[s][i];
                float ta = dd[ja] - sh;
                sum0 += __expf(-er * ta * ta) * fcR[ja];
            }
            acc[c] = 0.25f * (sum0 + sum1);
        }
    } else {
        const int t2   = tid - 32;           // 0..95
        const int lane = tid & 31;
        const int zr   = lane & 7;           // z rotation
        const int ar   = (lane >> 3) & 3;    // a rotation
        float shAr[4];
        #pragma unroll
        for (int ai = 0; ai < 4; ai++) shAr[ai] = shA[(ai + ar) & 3];

        const float etaA = sP[1];
        const float zeta = sP[2];
        const bool  z32  = (zeta == 32.0f);

        const int n     = ncnt;
        const int npair = (n * (n - 1)) >> 1;
        const float fn  = (float)(2 * n - 1);

        for (int p = t2; p < npair; p += 96) {
            // closed-form upper-triangular decode with one-step fixup
            float disc = fn * fn - 8.0f * (float)p;
            int jj = (int)(0.5f * (fn - sqrtf(disc)));
            int off = (jj * (2 * n - 1 - jj)) >> 1;
            if (off > p) { jj--; off = (jj * (2 * n - 1 - jj)) >> 1; }
            else {
                int o2 = ((jj + 1) * (2 * n - 2 - jj)) >> 1;
                if (o2 <= p) { jj++; off = o2; }
            }
            int kk = jj + 1 + (p - off);
            int j = nidx[jj], k = nidx[kk];

            float d1 = dd[j], d2 = dd[k];
            float dot = ddx[j] * ddx[k] + ddy[j] * ddy[k] + ddz[j] * ddz[k];
            float inv = __frcp_rn(fmaxf(d1, 1e-8f) * fmaxf(d2, 1e-8f));
            float ca  = 0.95f * dot * inv;
            float sa  = sqrtf(fmaxf(1.0f - ca * ca, 0.0f));
            float dm  = 0.5f * (d1 + d2);
            float fcj2 = 2.0f * fcA[j] * fcA[k];

            int s1 = ssp[j], s2 = ssp[k];
            int lo = min(s1, s2), hi = max(s1, s2);
            int pidx = ((lo * (2 * NSPEC + 1 - lo)) >> 1) + (hi - lo);
            float* a0 = &acc[RAD_LEN + pidx * ANG_SUB];

            float f2r[4];
            #pragma unroll
            for (int ai = 0; ai < 4; ai++) {
                float t = dm - shAr[ai];
                f2r[ai] = __expf(-etaA * t * t) * fcj2;
            }

            #pragma unroll
            for (int zi = 0; zi < 8; zi++) {
                int z = (zi + zr) & 7;
                float c = ca * czv[z] + sa * szv[z];
                float x = 0.5f + 0.5f * c;
                float f1;
                if (z32) {
                    float x2 = x * x, x4 = x2 * x2, x8 = x4 * x4, x16 = x8 * x8;
                    f1 = x16 * x16;
                } else {
                    f1 = __powf(x, zeta);
                }
                #pragma unroll
                for (int ai = 0; ai < 4; ai++) {
                    int a = (ai + ar) & 3;
                    atomicAdd(&a0[a * 8 + z], f1 * f2r[ai]);
                }
            }
        }
    }
    __syncthreads();

    // ---- coalesced output ----
    float* o = out + (size_t)blockIdx.x * AEV_LEN;
    o[tid] = acc[tid];
    o[tid + 128] = acc[tid + 128];
    o[tid + 256] = acc[tid + 256];
}

extern "C" void kernel_launch(void* const* d_in, const int* in_sizes, int n_in,
                              void* d_out, int out_size) {
    const float* coords = (const float*)d_in[0];
    const float* EtaR   = (const float*)d_in[1];
    const float* ShfR   = (const float*)d_in[2];
    const float* EtaA   = (const float*)d_in[3];
    const float* Zeta   = (const float*)d_in[4];
    const float* ShfA   = (const float*)d_in[5];
    const float* ShfZ   = (const float*)d_in[6];
    const int*   spec   = (const int*)d_in[7];
    float* out = (float*)d_out;

    int M = in_sizes[0] / (ATOMS_N * 3);
    aev_kernel<<<M * ATOMS_N, 128>>>(coords, EtaR, ShfR, EtaA, Zeta, ShfA, ShfZ, spec, out);
}

// round 4
// speedup vs baseline: 1.2220x; 1.2220x over previous
#include <cuda_runtime.h>
#include <cuda_bf16.h>
#include <math.h>

#define ATOMS_N 48
#define NSPEC 4
#define RAD_LEN 64
#define ANG_SUB 32
#define ANG_LEN 320
#define AEV_LEN 384
#define RCR_F 5.2f
#define RCA_F 3.5f
#define PI_F 3.14159265358979323846f

__global__ __launch_bounds__(128, 11)
void aev_kernel(const float* __restrict__ coords,
                const float* __restrict__ EtaR,
                const float* __restrict__ ShfR,
                const float* __restrict__ EtaA,
                const float* __restrict__ Zeta,
                const float* __restrict__ ShfA,
                const float* __restrict__ ShfZ,
                const int*   __restrict__ species,
                float* __restrict__ out)
{
    __shared__ float sc[ATOMS_N * 3];
    __shared__ float ddx[ATOMS_N], ddy[ATOMS_N], ddz[ATOMS_N];
    __shared__ float dd[ATOMS_N], fcA[ATOMS_N], fcR[ATOMS_N];
    __shared__ int   ssp[ATOMS_N], nidx[ATOMS_N];
    __shared__ int   ncnt;
    __shared__ float acc[AEV_LEN];
    __shared__ float shR[16], shA[4], czv[8], szv[8];
    __shared__ float sP[3]; // etaR, etaA, zeta

    const int tid = threadIdx.x;
    const int m  = blockIdx.x / ATOMS_N;
    const int ci = blockIdx.x % ATOMS_N;

    // ---- coalesced loads + params + zero accumulator ----
    sc[tid] = coords[m * 144 + tid];
    if (tid < 16) sc[128 + tid] = coords[m * 144 + 128 + tid];
    if (tid < ATOMS_N) ssp[tid] = species[m * ATOMS_N + tid];
    if (tid >= 64 && tid < 80) shR[tid - 64] = ShfR[tid - 64];
    if (tid >= 80 && tid < 84) shA[tid - 80] = ShfA[tid - 80];
    if (tid >= 88 && tid < 96) {
        float v = ShfZ[tid - 88];
        czv[tid - 88] = cosf(v);
        szv[tid - 88] = sinf(v);
    }
    if (tid == 96) sP[0] = EtaR[0];
    if (tid == 97) sP[1] = EtaA[0];
    if (tid == 98) sP[2] = Zeta[0];
    acc[tid] = 0.0f; acc[tid + 128] = 0.0f; acc[tid + 256] = 0.0f;
    __syncthreads();

    // ---- warp 0: geometry for all 48 atoms (2 per lane) + ballot compaction ----
    if (tid < 32) {
        const int lane = tid;
        const float cx = sc[3 * ci], cy = sc[3 * ci + 1], cz = sc[3 * ci + 2];

        float x0 = sc[3 * lane] - cx;
        float y0 = sc[3 * lane + 1] - cy;
        float z0 = sc[3 * lane + 2] - cz;
        float d0 = sqrtf(x0 * x0 + y0 * y0 + z0 * z0);
        ddx[lane] = x0; ddy[lane] = y0; ddz[lane] = z0; dd[lane] = d0;
        fcR[lane] = 0.5f * __cosf(d0 * (PI_F / RCR_F)) + 0.5f;
        fcA[lane] = 0.5f * __cosf(d0 * (PI_F / RCA_F)) + 0.5f;

        float d1 = 1e30f;
        const int j1 = 32 + lane;
        if (lane < 16) {
            float x1 = sc[3 * j1] - cx;
            float y1 = sc[3 * j1 + 1] - cy;
            float z1 = sc[3 * j1 + 2] - cz;
            d1 = sqrtf(x1 * x1 + y1 * y1 + z1 * z1);
            ddx[j1] = x1; ddy[j1] = y1; ddz[j1] = z1; dd[j1] = d1;
            fcR[j1] = 0.5f * __cosf(d1 * (PI_F / RCR_F)) + 0.5f;
            fcA[j1] = 0.5f * __cosf(d1 * (PI_F / RCA_F)) + 0.5f;
        }

        bool v0 = (lane != ci) && (d0 <= RCA_F);
        bool v1 = (lane < 16) && (j1 != ci) && (d1 <= RCA_F);
        unsigned m0 = __ballot_sync(0xffffffffu, v0);
        unsigned m1 = __ballot_sync(0xffffffffu, v1);
        unsigned lt = (1u << lane) - 1u;
        int c0 = __popc(m0);
        if (v0) nidx[__popc(m0 & lt)] = lane;
        if (v1) nidx[c0 + __popc(m1 & lt)] = j1;
        if (lane == 0) ncnt = c0 + __popc(m1);
    }
    __syncthreads();

    // ---- fused phase: warps 0-1 radial channels, warps 2-3 angular pairs ----
    if (tid < RAD_LEN) {
        const int s = tid >> 4;
        const int r = tid & 15;
        const float er = sP[0];
        const float sh = shR[r];
        float sum = 0.0f;
        #pragma unroll 4
        for (int j = 0; j < ATOMS_N; j++) {
            float d = dd[j];
            float t = d - sh;
            float e = __expf(-er * t * t) * fcR[j];
            bool ok = (j != ci) & (d <= RCR_F) & (ssp[j] == s);
            sum += ok ? e : 0.0f;
        }
        acc[tid] = 0.25f * sum;
    } else {
        const int t2   = tid - 64;
        const int lane = tid & 31;
        const int zr   = lane & 7;         // z rotation
        const int ar   = (lane >> 3) & 3;  // a rotation

        const float etaA = sP[1];
        const float zeta = sP[2];
        const bool  z32  = (zeta == 32.0f);

        const int n     = ncnt;
        const int npair = (n * (n - 1)) >> 1;
        const float fn  = (float)(2 * n - 1);

        for (int p = t2; p < npair; p += 64) {
            // closed-form upper-triangular decode with one-step fixup
            float disc = fn * fn - 8.0f * (float)p;
            int jj = (int)(0.5f * (fn - sqrtf(disc)));
            int off = (jj * (2 * n - 1 - jj)) >> 1;
            if (off > p) { jj--; off = (jj * (2 * n - 1 - jj)) >> 1; }
            else {
                int o2 = ((jj + 1) * (2 * n - 2 - jj)) >> 1;
                if (o2 <= p) { jj++; off = o2; }
            }
            int kk = jj + 1 + (p - off);
            int j = nidx[jj], k = nidx[kk];

            float d1 = dd[j], d2 = dd[k];
            float dot = ddx[j] * ddx[k] + ddy[j] * ddy[k] + ddz[j] * ddz[k];
            float inv = __frcp_rn(fmaxf(d1, 1e-8f) * fmaxf(d2, 1e-8f));
            float ca  = 0.95f * dot * inv;
            float sa  = sqrtf(fmaxf(1.0f - ca * ca, 0.0f));
            float dm  = 0.5f * (d1 + d2);
            float fcj2 = 2.0f * fcA[j] * fcA[k];

            int s1 = ssp[j], s2 = ssp[k];
            int lo = min(s1, s2), hi = max(s1, s2);
            int pidx = ((lo * (2 * NSPEC + 1 - lo)) >> 1) + (hi - lo);
            float* a0 = &acc[RAD_LEN + pidx * ANG_SUB];

            float f2r[4];
            #pragma unroll
            for (int ai = 0; ai < 4; ai++) {
                float t = dm - shA[(ai + ar) & 3];
                f2r[ai] = __expf(-etaA * t * t) * fcj2;
            }

            #pragma unroll
            for (int zi = 0; zi < 8; zi++) {
                int z = (zi + zr) & 7;
                float c = ca * czv[z] + sa * szv[z];
                float x = 0.5f + 0.5f * c;
                float f1;
                if (z32) {
                    float x2 = x * x, x4 = x2 * x2, x8 = x4 * x4, x16 = x8 * x8;
                    f1 = x16 * x16;
                } else {
                    f1 = __powf(x, zeta);
                }
                #pragma unroll
                for (int ai = 0; ai < 4; ai++) {
                    int a = (ai + ar) & 3;
                    atomicAdd(&a0[a * 8 + z], f1 * f2r[ai]);
                }
            }
        }
    }
    __syncthreads();

    // ---- coalesced output ----
    float* o = out + (size_t)blockIdx.x * AEV_LEN;
    o[tid] = acc[tid];
    o[tid + 128] = acc[tid + 128];
    o[tid + 256] = acc[tid + 256];
}

extern "C" void kernel_launch(void* const* d_in, const int* in_sizes, int n_in,
                              void* d_out, int out_size) {
    const float* coords = (const float*)d_in[0];
    const float* EtaR   = (const float*)d_in[1];
    const float* ShfR   = (const float*)d_in[2];
    const float* EtaA   = (const float*)d_in[3];
    const float* Zeta   = (const float*)d_in[4];
    const float* ShfA   = (const float*)d_in[5];
    const float* ShfZ   = (const float*)d_in[6];
    const int*   spec   = (const int*)d_in[7];
    float* out = (float*)d_out;

    int M = in_sizes[0] / (ATOMS_N * 3);
    aev_kernel<<<M * ATOMS_N, 128>>>(coords, EtaR, ShfR, EtaA, Zeta, ShfA, ShfZ, spec, out);
}

// round 5
// speedup vs baseline: 1.3431x; 1.0991x over previous
#include <cuda_runtime.h>
#include <cuda_bf16.h>
#include <math.h>

#define ATOMS_N 48
#define NSPEC 4
#define RAD_LEN 64
#define ANG_SUB 32
#define ANG_LEN 320
#define AEV_LEN 384
#define RCR_F 5.2f
#define RCA_F 3.5f
#define PI_F 3.14159265358979323846f

__global__ __launch_bounds__(128, 11)
void aev_kernel(const float* __restrict__ coords,
                const float* __restrict__ EtaR,
                const float* __restrict__ ShfR,
                const float* __restrict__ EtaA,
                const float* __restrict__ Zeta,
                const float* __restrict__ ShfA,
                const float* __restrict__ ShfZ,
                const int*   __restrict__ species,
                float* __restrict__ out)
{
    __shared__ float sc[ATOMS_N * 3];
    __shared__ float ddx[ATOMS_N], ddy[ATOMS_N], ddz[ATOMS_N];
    __shared__ float dd[ATOMS_N], fcA[ATOMS_N], fcR[ATOMS_N];
    __shared__ int   ssp[ATOMS_N], nidx[ATOMS_N];
    __shared__ int   ncnt;
    __shared__ float acc[AEV_LEN];
    __shared__ float shR[16], shA[4], czv[8], szv[8];
    __shared__ float sP[3]; // etaR, etaA, zeta

    const int tid = threadIdx.x;
    const int m  = blockIdx.x / ATOMS_N;
    const int ci = blockIdx.x % ATOMS_N;

    // ---- coalesced loads + params + zero accumulator ----
    sc[tid] = coords[m * 144 + tid];
    if (tid < 16) sc[128 + tid] = coords[m * 144 + 128 + tid];
    if (tid < ATOMS_N) ssp[tid] = species[m * ATOMS_N + tid];
    if (tid >= 64 && tid < 80) shR[tid - 64] = ShfR[tid - 64];
    if (tid >= 80 && tid < 84) shA[tid - 80] = ShfA[tid - 80];
    if (tid >= 88 && tid < 96) {
        float v = ShfZ[tid - 88];
        czv[tid - 88] = cosf(v);
        szv[tid - 88] = sinf(v);
    }
    if (tid == 96) sP[0] = EtaR[0];
    if (tid == 97) sP[1] = EtaA[0];
    if (tid == 98) sP[2] = Zeta[0];
    acc[tid] = 0.0f; acc[tid + 128] = 0.0f; acc[tid + 256] = 0.0f;
    __syncthreads();

    // ---- warp 0: geometry for all 48 atoms (2 per lane) + ballot compaction ----
    if (tid < 32) {
        const int lane = tid;
        const float cx = sc[3 * ci], cy = sc[3 * ci + 1], cz = sc[3 * ci + 2];

        float x0 = sc[3 * lane] - cx;
        float y0 = sc[3 * lane + 1] - cy;
        float z0 = sc[3 * lane + 2] - cz;
        float d0 = sqrtf(x0 * x0 + y0 * y0 + z0 * z0);
        ddx[lane] = x0; ddy[lane] = y0; ddz[lane] = z0; dd[lane] = d0;
        fcR[lane] = 0.5f * __cosf(d0 * (PI_F / RCR_F)) + 0.5f;
        fcA[lane] = 0.5f * __cosf(d0 * (PI_F / RCA_F)) + 0.5f;

        float d1 = 1e30f;
        const int j1 = 32 + lane;
        if (lane < 16) {
            float x1 = sc[3 * j1] - cx;
            float y1 = sc[3 * j1 + 1] - cy;
            float z1 = sc[3 * j1 + 2] - cz;
            d1 = sqrtf(x1 * x1 + y1 * y1 + z1 * z1);
            ddx[j1] = x1; ddy[j1] = y1; ddz[j1] = z1; dd[j1] = d1;
            fcR[j1] = 0.5f * __cosf(d1 * (PI_F / RCR_F)) + 0.5f;
            fcA[j1] = 0.5f * __cosf(d1 * (PI_F / RCA_F)) + 0.5f;
        }

        bool v0 = (lane != ci) && (d0 <= RCA_F);
        bool v1 = (lane < 16) && (j1 != ci) && (d1 <= RCA_F);
        unsigned m0 = __ballot_sync(0xffffffffu, v0);
        unsigned m1 = __ballot_sync(0xffffffffu, v1);
        unsigned lt = (1u << lane) - 1u;
        int c0 = __popc(m0);
        if (v0) nidx[__popc(m0 & lt)] = lane;
        if (v1) nidx[c0 + __popc(m1 & lt)] = j1;
        if (lane == 0) ncnt = c0 + __popc(m1);
    }
    __syncthreads();

    // ---- radial: all 128 threads, 2 threads per channel, 24 atoms each ----
    // Writes acc[0..64); angular below writes acc[64..384) — disjoint, so no
    // barrier needed between phases: threads fall through for natural balance.
    {
        const int c    = tid >> 1;          // channel 0..63
        const int half = tid & 1;
        const int s    = c >> 4;
        const float er = sP[0];
        const float sh = shR[c & 15];
        const int j0 = half * 24;
        float sum = 0.0f;
        #pragma unroll 4
        for (int jj = 0; jj < 24; jj++) {
            int j = j0 + jj;
            float d = dd[j];
            float t = d - sh;
            float e = __expf(-er * t * t) * fcR[j];
            bool ok = (j != ci) & (d <= RCR_F) & (ssp[j] == s);
            sum += ok ? e : 0.0f;
        }
        atomicAdd(&acc[c], 0.25f * sum);
    }

    // ---- angular: all 128 threads, one pair per work item ----
    {
        const int lane = tid & 31;
        const int zr   = lane & 7;         // z rotation
        const int ar   = (lane >> 3) & 3;  // a rotation

        const float etaA = sP[1];
        const float zeta = sP[2];
        const bool  z32  = (zeta == 32.0f);

        const int n     = ncnt;
        const int npair = (n * (n - 1)) >> 1;
        const float fn  = (float)(2 * n - 1);

        for (int p = tid; p < npair; p += 128) {
            // closed-form upper-triangular decode with one-step fixup
            float disc = fn * fn - 8.0f * (float)p;
            int jj = (int)(0.5f * (fn - sqrtf(disc)));
            int off = (jj * (2 * n - 1 - jj)) >> 1;
            if (off > p) { jj--; off = (jj * (2 * n - 1 - jj)) >> 1; }
            else {
                int o2 = ((jj + 1) * (2 * n - 2 - jj)) >> 1;
                if (o2 <= p) { jj++; off = o2; }
            }
            int kk = jj + 1 + (p - off);
            int j = nidx[jj], k = nidx[kk];

            float d1 = dd[j], d2 = dd[k];
            float dot = ddx[j] * ddx[k] + ddy[j] * ddy[k] + ddz[j] * ddz[k];
            float inv = __frcp_rn(fmaxf(d1, 1e-8f) * fmaxf(d2, 1e-8f));
            float ca  = 0.95f * dot * inv;
            float sa  = sqrtf(fmaxf(1.0f - ca * ca, 0.0f));
            float dm  = 0.5f * (d1 + d2);
            float fcj2 = 2.0f * fcA[j] * fcA[k];

            int s1 = ssp[j], s2 = ssp[k];
            int lo = min(s1, s2), hi = max(s1, s2);
            int pidx = ((lo * (2 * NSPEC + 1 - lo)) >> 1) + (hi - lo);
            float* a0 = &acc[RAD_LEN + pidx * ANG_SUB];

            float f2r[4];
            #pragma unroll
            for (int ai = 0; ai < 4; ai++) {
                float t = dm - shA[(ai + ar) & 3];
                f2r[ai] = __expf(-etaA * t * t) * fcj2;
            }

            #pragma unroll
            for (int zi = 0; zi < 8; zi++) {
                int z = (zi + zr) & 7;
                float c = ca * czv[z] + sa * szv[z];
                float x = 0.5f + 0.5f * c;
                float f1;
                if (z32) {
                    float x2 = x * x, x4 = x2 * x2, x8 = x4 * x4, x16 = x8 * x8;
                    f1 = x16 * x16;
                } else {
                    f1 = __powf(x, zeta);
                }
                #pragma unroll
                for (int ai = 0; ai < 4; ai++) {
                    int a = (ai + ar) & 3;
                    atomicAdd(&a0[a * 8 + z], f1 * f2r[ai]);
                }
            }
        }
    }
    __syncthreads();

    // ---- coalesced output ----
    float* o = out + (size_t)blockIdx.x * AEV_LEN;
    o[tid] = acc[tid];
    o[tid + 128] = acc[tid + 128];
    o[tid + 256] = acc[tid + 256];
}

extern "C" void kernel_launch(void* const* d_in, const int* in_sizes, int n_in,
                              void* d_out, int out_size) {
    const float* coords = (const float*)d_in[0];
    const float* EtaR   = (const float*)d_in[1];
    const float* ShfR   = (const float*)d_in[2];
    const float* EtaA   = (const float*)d_in[3];
    const float* Zeta   = (const float*)d_in[4];
    const float* ShfA   = (const float*)d_in[5];
    const float* ShfZ   = (const float*)d_in[6];
    const int*   spec   = (const int*)d_in[7];
    float* out = (float*)d_out;

    int M = in_sizes[0] / (ATOMS_N * 3);
    aev_kernel<<<M * ATOMS_N, 128>>>(coords, EtaR, ShfR, EtaA, Zeta, ShfA, ShfZ, spec, out);
}

// round 6
// speedup vs baseline: 1.5776x; 1.1746x over previous
#include <cuda_runtime.h>
#include <cuda_bf16.h>
#include <math.h>

#define ATOMS_N 48
#define NSPEC 4
#define RAD_LEN 64
#define ANG_SUB 32
#define ANG_LEN 320
#define AEV_LEN 384
#define RCR_F 5.2f
#define RCA_F 3.5f
#define PI_F 3.14159265358979323846f

__global__ __launch_bounds__(128, 11)
void aev_kernel(const float* __restrict__ coords,
                const float* __restrict__ EtaR,
                const float* __restrict__ ShfR,
                const float* __restrict__ EtaA,
                const float* __restrict__ Zeta,
                const float* __restrict__ ShfA,
                const float* __restrict__ ShfZ,
                const int*   __restrict__ species,
                float* __restrict__ out)
{
    __shared__ float sc[ATOMS_N * 3];
    __shared__ float dd[ATOMS_N], fcR[ATOMS_N];
    __shared__ int   ssp[ATOMS_N];
    // compacted angular-neighbor arrays
    __shared__ float adx[ATOMS_N], ady[ATOMS_N], adz[ATOMS_N];
    __shared__ float ad[ATOMS_N], afc[ATOMS_N];
    __shared__ int   asp[ATOMS_N];
    __shared__ int   ncnt;
    __shared__ float acc[AEV_LEN];
    __shared__ float shR[16], shA[4], czv[8], szv[8];
    __shared__ float sP[3]; // etaR, etaA, zeta

    const int tid = threadIdx.x;
    const int m  = blockIdx.x / ATOMS_N;
    const int ci = blockIdx.x % ATOMS_N;

    // ---- coalesced loads + params + zero accumulator ----
    sc[tid] = coords[m * 144 + tid];
    if (tid < 16) sc[128 + tid] = coords[m * 144 + 128 + tid];
    if (tid < ATOMS_N) ssp[tid] = species[m * ATOMS_N + tid];
    if (tid >= 64 && tid < 80) shR[tid - 64] = ShfR[tid - 64];
    if (tid >= 80 && tid < 84) shA[tid - 80] = ShfA[tid - 80];
    if (tid >= 88 && tid < 96) {
        float v = ShfZ[tid - 88];
        czv[tid - 88] = cosf(v);
        szv[tid - 88] = sinf(v);
    }
    if (tid == 96) sP[0] = EtaR[0];
    if (tid == 97) sP[1] = EtaA[0];
    if (tid == 98) sP[2] = Zeta[0];
    acc[tid] = 0.0f; acc[tid + 128] = 0.0f; acc[tid + 256] = 0.0f;
    __syncthreads();

    // ---- warp 0: geometry + ballot compaction (writes compacted arrays) ----
    if (tid < 32) {
        const int lane = tid;
        const unsigned lt = (1u << lane) - 1u;
        const float cx = sc[3 * ci], cy = sc[3 * ci + 1], cz = sc[3 * ci + 2];

        float x0 = sc[3 * lane] - cx;
        float y0 = sc[3 * lane + 1] - cy;
        float z0 = sc[3 * lane + 2] - cz;
        float d0 = sqrtf(x0 * x0 + y0 * y0 + z0 * z0);
        dd[lane] = d0;
        fcR[lane] = 0.5f * __cosf(d0 * (PI_F / RCR_F)) + 0.5f;
        float fa0 = 0.5f * __cosf(d0 * (PI_F / RCA_F)) + 0.5f;

        float d1 = 1e30f, x1 = 0.f, y1 = 0.f, z1 = 0.f, fa1 = 0.f;
        const int j1 = 32 + lane;
        if (lane < 16) {
            x1 = sc[3 * j1] - cx;
            y1 = sc[3 * j1 + 1] - cy;
            z1 = sc[3 * j1 + 2] - cz;
            d1 = sqrtf(x1 * x1 + y1 * y1 + z1 * z1);
            dd[j1] = d1;
            fcR[j1] = 0.5f * __cosf(d1 * (PI_F / RCR_F)) + 0.5f;
            fa1 = 0.5f * __cosf(d1 * (PI_F / RCA_F)) + 0.5f;
        }

        bool v0 = (lane != ci) && (d0 <= RCA_F);
        bool v1 = (lane < 16) && (j1 != ci) && (d1 <= RCA_F);
        unsigned m0 = __ballot_sync(0xffffffffu, v0);
        unsigned m1 = __ballot_sync(0xffffffffu, v1);
        int c0 = __popc(m0);
        if (v0) {
            int p = __popc(m0 & lt);
            adx[p] = x0; ady[p] = y0; adz[p] = z0;
            ad[p] = d0; afc[p] = fa0; asp[p] = ssp[lane];
        }
        if (v1) {
            int p = c0 + __popc(m1 & lt);
            adx[p] = x1; ady[p] = y1; adz[p] = z1;
            ad[p] = d1; afc[p] = fa1; asp[p] = ssp[j1];
        }
        if (lane == 0) ncnt = c0 + __popc(m1);
    }
    __syncthreads();

    // ---- radial: atom-centric, 768 work items, 6 per thread, fixed r ----
    // Writes acc[0..64); angular writes acc[64..384) — disjoint, no barrier.
    {
        const int r  = tid & 15;
        const int j0 = tid >> 4;
        const float er = sP[0];
        const float sh = shR[r];
        #pragma unroll
        for (int i = 0; i < 6; i++) {
            int j = j0 + (i << 3);
            float d = dd[j];
            float t = d - sh;
            float e = 0.25f * __expf(-er * t * t) * fcR[j];
            if ((j != ci) & (d <= RCR_F))
                atomicAdd(&acc[(ssp[j] << 4) + r], e);
        }
    }

    // ---- angular: all 128 threads, one pair per work item ----
    {
        const int lane = tid & 31;
        const int zr   = lane & 7;         // z rotation
        const int ar   = (lane >> 3) & 3;  // a rotation

        const float etaA = sP[1];
        const float zeta = sP[2];
        const bool  z32  = (zeta == 32.0f);

        const int n     = ncnt;
        const int npair = (n * (n - 1)) >> 1;
        const float fn  = (float)(2 * n - 1);

        for (int p = tid; p < npair; p += 128) {
            // closed-form upper-triangular decode with one-step fixup
            float disc = fn * fn - 8.0f * (float)p;
            int jj = (int)(0.5f * (fn - sqrtf(disc)));
            int off = (jj * (2 * n - 1 - jj)) >> 1;
            if (off > p) { jj--; off = (jj * (2 * n - 1 - jj)) >> 1; }
            else {
                int o2 = ((jj + 1) * (2 * n - 2 - jj)) >> 1;
                if (o2 <= p) { jj++; off = o2; }
            }
            int kk = jj + 1 + (p - off);

            float d1 = ad[jj], d2 = ad[kk];
            float dot = adx[jj] * adx[kk] + ady[jj] * ady[kk] + adz[jj] * adz[kk];
            float inv = __frcp_rn(fmaxf(d1, 1e-8f) * fmaxf(d2, 1e-8f));
            float ca  = 0.95f * dot * inv;
            float sa  = sqrtf(fmaxf(1.0f - ca * ca, 0.0f));
            float dm  = 0.5f * (d1 + d2);
            float fcj2 = 2.0f * afc[jj] * afc[kk];

            int s1 = asp[jj], s2 = asp[kk];
            int lo = min(s1, s2), hi = max(s1, s2);
            int pidx = ((lo * (2 * NSPEC + 1 - lo)) >> 1) + (hi - lo);
            float* a0 = &acc[RAD_LEN + pidx * ANG_SUB];

            float f2r[4];
            #pragma unroll
            for (int ai = 0; ai < 4; ai++) {
                float t = dm - shA[(ai + ar) & 3];
                f2r[ai] = __expf(-etaA * t * t) * fcj2;
            }

            #pragma unroll
            for (int zi = 0; zi < 8; zi++) {
                int z = (zi + zr) & 7;
                float c = ca * czv[z] + sa * szv[z];
                float x = 0.5f + 0.5f * c;
                float f1;
                if (z32) {
                    float x2 = x * x, x4 = x2 * x2, x8 = x4 * x4, x16 = x8 * x8;
                    f1 = x16 * x16;
                } else {
                    f1 = __powf(x, zeta);
                }
                #pragma unroll
                for (int ai = 0; ai < 4; ai++) {
                    int a = (ai + ar) & 3;
                    atomicAdd(&a0[a * 8 + z], f1 * f2r[ai]);
                }
            }
        }
    }
    __syncthreads();

    // ---- coalesced output ----
    float* o = out + (size_t)blockIdx.x * AEV_LEN;
    o[tid] = acc[tid];
    o[tid + 128] = acc[tid + 128];
    o[tid + 256] = acc[tid + 256];
}

extern "C" void kernel_launch(void* const* d_in, const int* in_sizes, int n_in,
                              void* d_out, int out_size) {
    const float* coords = (const float*)d_in[0];
    const float* EtaR   = (const float*)d_in[1];
    const float* ShfR   = (const float*)d_in[2];
    const float* EtaA   = (const float*)d_in[3];
    const float* Zeta   = (const float*)d_in[4];
    const float* ShfA   = (const float*)d_in[5];
    const float* ShfZ   = (const float*)d_in[6];
    const int*   spec   = (const int*)d_in[7];
    float* out = (float*)d_out;

    int M = in_sizes[0] / (ATOMS_N * 3);
    aev_kernel<<<M * ATOMS_N, 128>>>(coords, EtaR, ShfR, EtaA, Zeta, ShfA, ShfZ, spec, out);
}